// round 12
// baseline (speedup 1.0000x reference)
#include <cuda_runtime.h>
#include <cuda_bf16.h>
#include <cstdint>

// Problem constants (fixed by the dataset)
#define NMAX   100000
#define EMAX   1600000
#define INCH   128
#define HIDCH  128
#define OUTCH  64

// ---------------- scratch (device globals; no allocation in kernel_launch) ----
__device__ int   g_counts [NMAX];
__device__ int   g_exc    [NMAX];
__device__ int   g_bsums  [512];
__device__ int   g_rowst  [NMAX + 1];
__device__ int   g_cursor [NMAX];
__device__ int   g_csrc   [EMAX];
__device__ float g_cnorm  [EMAX];
__device__ float g_dinv   [NMAX];
__device__ float g_h1  [(size_t)NMAX * HIDCH];
__device__ float g_hbuf[(size_t)NMAX * HIDCH];
__device__ float g_h2  [(size_t)NMAX * OUTCH];

__device__ __forceinline__ uint32_t pack_bf16x2(float a, float b) {
    __nv_bfloat162 t = __floats2bfloat162_rn(a, b);
    return *reinterpret_cast<uint32_t*>(&t);
}

// ---------------- setup kernels -----------------------------------------------
__global__ void zero_counts_k(int* __restrict__ counts, int n) {
    int i = blockIdx.x * blockDim.x + threadIdx.x;
    if (i < n) counts[i] = 0;
}

__global__ void count_k(const int* __restrict__ dst, int* counts, int e, int n) {
    int i = blockIdx.x * blockDim.x + threadIdx.x;
    if (i < e) {
        int d = dst[i];
        if ((unsigned)d < (unsigned)n) atomicAdd(&counts[d], 1);
    }
}

__global__ void dinv_k(const int* __restrict__ counts, float* __restrict__ dinv, int n) {
    int i = blockIdx.x * blockDim.x + threadIdx.x;
    if (i < n) dinv[i] = rsqrtf(1.0f + (float)counts[i]);   // +1 self-loop
}

// ---------------- exclusive scan (3 kernels, 256-wide blocks) -------------------
__global__ void scan_block_k(const int* __restrict__ counts, int* __restrict__ exc,
                             int* __restrict__ bsums, int n) {
    __shared__ int sh[256];
    int i = blockIdx.x * 256 + threadIdx.x;
    int v = (i < n) ? counts[i] : 0;
    sh[threadIdx.x] = v;
    __syncthreads();
#pragma unroll
    for (int off = 1; off < 256; off <<= 1) {
        int t = (threadIdx.x >= off) ? sh[threadIdx.x - off] : 0;
        __syncthreads();
        sh[threadIdx.x] += t;
        __syncthreads();
    }
    if (i < n) exc[i] = sh[threadIdx.x] - v;
    if (threadIdx.x == 255) bsums[blockIdx.x] = sh[255];
}

__global__ void scan_sums_k(int* __restrict__ bsums, int nb) {
    __shared__ int sh[512];
    int v = (threadIdx.x < nb) ? bsums[threadIdx.x] : 0;
    sh[threadIdx.x] = v;
    __syncthreads();
#pragma unroll
    for (int off = 1; off < 512; off <<= 1) {
        int t = (threadIdx.x >= off) ? sh[threadIdx.x - off] : 0;
        __syncthreads();
        sh[threadIdx.x] += t;
        __syncthreads();
    }
    if (threadIdx.x < nb) bsums[threadIdx.x] = sh[threadIdx.x] - v;  // exclusive
}

__global__ void scan_add_k(const int* __restrict__ exc, const int* __restrict__ bsums,
                           int* __restrict__ rowst, int* __restrict__ cursor,
                           int n, int e) {
    int i = blockIdx.x * 256 + threadIdx.x;
    if (i < n) {
        int r = exc[i] + bsums[i >> 8];
        rowst[i]  = r;
        cursor[i] = r;
    }
    if (i == 0) rowst[n] = e;
}

// ---------------- CSR fill ------------------------------------------------------
__global__ void fill_k(const int* __restrict__ src, const int* __restrict__ dst,
                       const float* __restrict__ dinv,
                       int* cursor, int* __restrict__ csrc, float* __restrict__ cnorm,
                       int e, int n) {
    int i = blockIdx.x * blockDim.x + threadIdx.x;
    if (i >= e) return;
    int s = src[i], d = dst[i];
    if ((unsigned)s >= (unsigned)n || (unsigned)d >= (unsigned)n) return;
    int pos = atomicAdd(&cursor[d], 1);
    csrc[pos]  = s;
    cnorm[pos] = dinv[s] * dinv[d];
}

// ---------------- HMMA bf16-split GEMM: H[n,BN] = A[n,128] @ W[128,BN] ----------
// D = Ahi*Whi + Ahi*Wlo + Alo*Whi, fp32 accumulators (mma.sync m16n8k16).
// 128-row tile/CTA, 8 warps (4m x 2n), warp tile 32 x BN/2.
// Smem: bf16 tiles with 68-word row stride -> frag LDS.32 is bank-conflict-free.
template<int BN>
__global__ void __launch_bounds__(256, 1)
gemm_tc_k(const float* __restrict__ A, const float* __restrict__ W,
          float* __restrict__ H, int n)
{
    constexpr int K  = 128;
    constexpr int SW = 68;                    // uint32 words per smem row (64 + 4 pad)
    constexpr int NT = BN / 16;               // n-tiles per warp (8 or 4)
    constexpr int ATILE = 128 * SW;           // words
    constexpr int BTILE = BN * SW;

    extern __shared__ uint32_t sm[];
    uint32_t* Ahi = sm;
    uint32_t* Alo = Ahi + ATILE;
    uint32_t* Bhi = Alo + ATILE;
    uint32_t* Blo = Bhi + BTILE;

    const int tid  = threadIdx.x;
    const int wid  = tid >> 5;
    const int lane = tid & 31;
    const int g    = lane >> 2;               // group id (0-7)
    const int c    = lane & 3;                // thread-in-group (0-3)
    const int warp_m = wid & 3;               // 4 m-warps
    const int warp_n = wid >> 2;              // 2 n-warps
    const int rowBase = blockIdx.x * 128;

    // --- load A tile: fp32 -> bf16 hi/lo, rows x 128 cols ---
#pragma unroll
    for (int it = 0; it < 16; it++) {
        int idx = it * 256 + tid;             // 128 rows x 32 float4 chunks
        int row = idx >> 5;
        int k4  = (idx & 31) * 4;
        float4 v = make_float4(0.f, 0.f, 0.f, 0.f);
        int grow = rowBase + row;
        if (grow < n)
            v = *reinterpret_cast<const float4*>(A + (size_t)grow * K + k4);
        __nv_bfloat16 hx = __float2bfloat16(v.x), hy = __float2bfloat16(v.y);
        __nv_bfloat16 hz = __float2bfloat16(v.z), hw = __float2bfloat16(v.w);
        int wo = row * SW + (k4 >> 1);
        Ahi[wo]     = pack_bf16x2(__bfloat162float(hx), __bfloat162float(hy));
        Ahi[wo + 1] = pack_bf16x2(__bfloat162float(hz), __bfloat162float(hw));
        Alo[wo]     = pack_bf16x2(v.x - __bfloat162float(hx), v.y - __bfloat162float(hy));
        Alo[wo + 1] = pack_bf16x2(v.z - __bfloat162float(hz), v.w - __bfloat162float(hw));
    }

    // --- load W transposed: Bs[nrow][k] from W[k][BN] ---
#pragma unroll
    for (int it = 0; it < BN * 32 / 256; it++) {
        int idx = it * 256 + tid;             // BN rows x 32 k4-chunks
        int nn  = idx >> 5;
        int k4  = (idx & 31) * 4;
        float w0 = W[(size_t)(k4 + 0) * BN + nn];
        float w1 = W[(size_t)(k4 + 1) * BN + nn];
        float w2 = W[(size_t)(k4 + 2) * BN + nn];
        float w3 = W[(size_t)(k4 + 3) * BN + nn];
        __nv_bfloat16 h0 = __float2bfloat16(w0), h1 = __float2bfloat16(w1);
        __nv_bfloat16 h2 = __float2bfloat16(w2), h3 = __float2bfloat16(w3);
        int wo = nn * SW + (k4 >> 1);
        Bhi[wo]     = pack_bf16x2(__bfloat162float(h0), __bfloat162float(h1));
        Bhi[wo + 1] = pack_bf16x2(__bfloat162float(h2), __bfloat162float(h3));
        Blo[wo]     = pack_bf16x2(w0 - __bfloat162float(h0), w1 - __bfloat162float(h1));
        Blo[wo + 1] = pack_bf16x2(w2 - __bfloat162float(h2), w3 - __bfloat162float(h3));
    }
    __syncthreads();

    float acc[2][NT][4];
#pragma unroll
    for (int mi = 0; mi < 2; mi++)
#pragma unroll
        for (int ni = 0; ni < NT; ni++)
#pragma unroll
            for (int q = 0; q < 4; q++) acc[mi][ni][q] = 0.0f;

    const int arow0 = warp_m * 32;            // warp's first row
    const int nbase = warp_n * (BN / 2);      // warp's first col

#pragma unroll
    for (int t = 0; t < 3; t++) {
        const uint32_t* Ab = (t == 2) ? Alo : Ahi;
        const uint32_t* Bb = (t == 1) ? Blo : Bhi;
#pragma unroll
        for (int ks = 0; ks < 8; ks++) {
            const int kw = ks * 8;            // word offset for k0 = 16*ks

            uint32_t a[2][4];
#pragma unroll
            for (int mi = 0; mi < 2; mi++) {
                int r0 = (arow0 + mi * 16 + g) * SW;
                int r1 = (arow0 + mi * 16 + 8 + g) * SW;
                a[mi][0] = Ab[r0 + kw + c];
                a[mi][1] = Ab[r1 + kw + c];
                a[mi][2] = Ab[r0 + kw + 4 + c];
                a[mi][3] = Ab[r1 + kw + 4 + c];
            }
            uint32_t b[NT][2];
#pragma unroll
            for (int ni = 0; ni < NT; ni++) {
                int nr = (nbase + ni * 8 + g) * SW;
                b[ni][0] = Bb[nr + kw + c];
                b[ni][1] = Bb[nr + kw + 4 + c];
            }
#pragma unroll
            for (int mi = 0; mi < 2; mi++)
#pragma unroll
                for (int ni = 0; ni < NT; ni++) {
                    float* d = acc[mi][ni];
                    asm volatile(
                        "mma.sync.aligned.m16n8k16.row.col.f32.bf16.bf16.f32 "
                        "{%0,%1,%2,%3}, {%4,%5,%6,%7}, {%8,%9}, {%0,%1,%2,%3};"
                        : "+f"(d[0]), "+f"(d[1]), "+f"(d[2]), "+f"(d[3])
                        : "r"(a[mi][0]), "r"(a[mi][1]), "r"(a[mi][2]), "r"(a[mi][3]),
                          "r"(b[ni][0]), "r"(b[ni][1]));
                }
        }
    }

    // --- epilogue: c0,c1 -> (row g, cols 2c..2c+1); c2,c3 -> row g+8 ---
#pragma unroll
    for (int mi = 0; mi < 2; mi++) {
        int row0 = rowBase + arow0 + mi * 16 + g;
        int row1 = row0 + 8;
#pragma unroll
        for (int ni = 0; ni < NT; ni++) {
            int col = nbase + ni * 8 + 2 * c;
            if (row0 < n)
                *reinterpret_cast<float2*>(H + (size_t)row0 * BN + col) =
                    make_float2(acc[mi][ni][0], acc[mi][ni][1]);
            if (row1 < n)
                *reinterpret_cast<float2*>(H + (size_t)row1 * BN + col) =
                    make_float2(acc[mi][ni][2], acc[mi][ni][3]);
        }
    }
}

// ---------------- gather: out[d] = sum_{e in row(d)} h[src_e]*norm_e
//                          + h[d]*dinv[d]^2 + bias   (optional relu)
template<int C4, bool RELU>
__global__ void __launch_bounds__(256)
gather_k(const int* __restrict__ rowst, const int* __restrict__ csrc,
         const float* __restrict__ cnorm, const float* __restrict__ h,
         const float* __restrict__ dinv, const float* __restrict__ bias,
         float* __restrict__ out, int n)
{
    constexpr int NPW = 32 / C4;                 // nodes per warp
    const int gtid = blockIdx.x * 256 + threadIdx.x;
    const int warp = gtid >> 5;
    const int lane = threadIdx.x & 31;
    const int sub  = lane / C4;
    const int ln   = lane % C4;
    const int node = warp * NPW + sub;
    if (node >= n) return;

    const float4* __restrict__ h4 = reinterpret_cast<const float4*>(h);
    const float4* __restrict__ b4 = reinterpret_cast<const float4*>(bias);

    const int start = rowst[node];
    const int end   = rowst[node + 1];

    float ax = 0.f, ay = 0.f, az = 0.f, aw = 0.f;

    int j = start;
    for (; j + 4 <= end; j += 4) {
        int   s0 = csrc[j],     s1 = csrc[j + 1], s2 = csrc[j + 2], s3 = csrc[j + 3];
        float n0 = cnorm[j],    n1 = cnorm[j + 1], n2 = cnorm[j + 2], n3 = cnorm[j + 3];
        float4 v0 = h4[(size_t)s0 * C4 + ln];
        float4 v1 = h4[(size_t)s1 * C4 + ln];
        float4 v2 = h4[(size_t)s2 * C4 + ln];
        float4 v3 = h4[(size_t)s3 * C4 + ln];
        ax += v0.x * n0 + v1.x * n1 + v2.x * n2 + v3.x * n3;
        ay += v0.y * n0 + v1.y * n1 + v2.y * n2 + v3.y * n3;
        az += v0.z * n0 + v1.z * n1 + v2.z * n2 + v3.z * n3;
        aw += v0.w * n0 + v1.w * n1 + v2.w * n2 + v3.w * n3;
    }
    for (; j < end; ++j) {
        int s = csrc[j];
        float nn = cnorm[j];
        float4 v = h4[(size_t)s * C4 + ln];
        ax += v.x * nn; ay += v.y * nn; az += v.z * nn; aw += v.w * nn;
    }

    float di  = dinv[node];
    float di2 = di * di;
    float4 hv = h4[(size_t)node * C4 + ln];
    float4 bb = b4[ln];
    ax += hv.x * di2 + bb.x;
    ay += hv.y * di2 + bb.y;
    az += hv.z * di2 + bb.z;
    aw += hv.w * di2 + bb.w;
    if (RELU) {
        ax = fmaxf(ax, 0.f); ay = fmaxf(ay, 0.f);
        az = fmaxf(az, 0.f); aw = fmaxf(aw, 0.f);
    }
    reinterpret_cast<float4*>(out)[(size_t)node * C4 + ln] = make_float4(ax, ay, az, aw);
}

// ---------------- launcher ----------------------------------------------------
extern "C" void kernel_launch(void* const* d_in, const int* in_sizes, int n_in,
                              void* d_out, int out_size)
{
    const float* x   = (const float*)d_in[0];
    const int*   ei  = (const int*)d_in[1];
    const float* W1  = (const float*)d_in[2];
    const float* b1  = (const float*)d_in[3];
    const float* W2  = (const float*)d_in[4];
    const float* b2  = (const float*)d_in[5];
    float*       out = (float*)d_out;

    const int n = in_sizes[0] / INCH;
    const int e = in_sizes[1] / 2;
    const int* src = ei;
    const int* dst = ei + e;

    int *counts, *exc, *bsums, *rowst, *cursor, *csrc;
    float *cnorm, *dinv, *h1, *hbuf, *h2;
    cudaGetSymbolAddress((void**)&counts, g_counts);
    cudaGetSymbolAddress((void**)&exc,    g_exc);
    cudaGetSymbolAddress((void**)&bsums,  g_bsums);
    cudaGetSymbolAddress((void**)&rowst,  g_rowst);
    cudaGetSymbolAddress((void**)&cursor, g_cursor);
    cudaGetSymbolAddress((void**)&csrc,   g_csrc);
    cudaGetSymbolAddress((void**)&cnorm,  g_cnorm);
    cudaGetSymbolAddress((void**)&dinv,   g_dinv);
    cudaGetSymbolAddress((void**)&h1,     g_h1);
    cudaGetSymbolAddress((void**)&hbuf,   g_hbuf);
    cudaGetSymbolAddress((void**)&h2,     g_h2);

    // dynamic smem: (2*128 + 2*BN) rows * 68 words * 4 bytes
    constexpr int SM1 = (2 * 128 + 2 * 128) * 68 * 4;   // 139264 (BN=128)
    constexpr int SM2 = (2 * 128 + 2 * 64)  * 68 * 4;   // 104448 (BN=64)
    cudaFuncSetAttribute(gemm_tc_k<128>, cudaFuncAttributeMaxDynamicSharedMemorySize, SM1);
    cudaFuncSetAttribute(gemm_tc_k<64>,  cudaFuncAttributeMaxDynamicSharedMemorySize, SM2);

    const int T = 256;
    const int nb = (n + 255) / 256;
    const int mtiles = (n + 127) / 128;

    // ---- degree + CSR build ----
    zero_counts_k<<<(n + T - 1) / T, T>>>(counts, n);
    count_k      <<<(e + T - 1) / T, T>>>(dst, counts, e, n);
    dinv_k       <<<(n + T - 1) / T, T>>>(counts, dinv, n);
    scan_block_k <<<nb, 256>>>(counts, exc, bsums, n);
    scan_sums_k  <<<1, 512>>>(bsums, nb);
    scan_add_k   <<<nb, 256>>>(exc, bsums, rowst, cursor, n, e);
    fill_k       <<<(e + T - 1) / T, T>>>(src, dst, dinv, cursor, csrc, cnorm, e, n);

    // ---- layer 1: h1 = x@W1 ; hbuf = relu(gather(h1) + self + b1) ----
    gemm_tc_k<128><<<mtiles, 256, SM1>>>(x, W1, h1, n);
    {
        constexpr int C4 = HIDCH / 4;            // 32 -> 1 node per warp
        int warps = n;
        gather_k<C4, true><<<(warps * 32 + 255) / 256, 256>>>(
            rowst, csrc, cnorm, h1, dinv, b1, hbuf, n);
    }

    // ---- layer 2: h2 = hbuf@W2 ; out = gather(h2) + self + b2 ----
    gemm_tc_k<64><<<mtiles, 256, SM2>>>(hbuf, W2, h2, n);
    {
        constexpr int C4 = OUTCH / 4;            // 16 -> 2 nodes per warp
        int warps = (n + 1) / 2;
        gather_k<C4, false><<<(warps * 32 + 255) / 256, 256>>>(
            rowst, csrc, cnorm, h2, dinv, b2, out, n);
    }
}

// round 14
// speedup vs baseline: 1.1126x; 1.1126x over previous
#include <cuda_runtime.h>
#include <cuda_fp16.h>
#include <cuda_bf16.h>
#include <cstdint>

// Problem constants (fixed by the dataset)
#define NMAX   100000
#define EMAX   1600000
#define INCH   128
#define HIDCH  128
#define OUTCH  64

// ---------------- scratch (device globals; no allocation in kernel_launch) ----
__device__ int    g_counts [NMAX];
__device__ int    g_exc    [NMAX];
__device__ int    g_bsums  [512];
__device__ int    g_rowst  [NMAX + 1];
__device__ int    g_cursor [NMAX];
__device__ int    g_csrc   [EMAX];
__device__ float  g_cnorm  [EMAX];
__device__ float  g_dinv   [NMAX];
__device__ __half g_h1  [(size_t)NMAX * HIDCH];
__device__ float  g_hbuf[(size_t)NMAX * HIDCH];
__device__ __half g_h2  [(size_t)NMAX * OUTCH];

// ---------------- setup kernels -----------------------------------------------
__global__ void zero_counts_k(int* __restrict__ counts, int n) {
    int i = blockIdx.x * blockDim.x + threadIdx.x;
    if (i < n) counts[i] = 0;
}

__global__ void count_k(const int* __restrict__ dst, int* counts, int e, int n) {
    int i = blockIdx.x * blockDim.x + threadIdx.x;
    if (i < e) {
        int d = dst[i];
        if ((unsigned)d < (unsigned)n) atomicAdd(&counts[d], 1);
    }
}

__global__ void dinv_k(const int* __restrict__ counts, float* __restrict__ dinv, int n) {
    int i = blockIdx.x * blockDim.x + threadIdx.x;
    if (i < n) dinv[i] = rsqrtf(1.0f + (float)counts[i]);   // +1 self-loop
}

// ---------------- exclusive scan (3 kernels, 256-wide blocks) -------------------
__global__ void scan_block_k(const int* __restrict__ counts, int* __restrict__ exc,
                             int* __restrict__ bsums, int n) {
    __shared__ int sh[256];
    int i = blockIdx.x * 256 + threadIdx.x;
    int v = (i < n) ? counts[i] : 0;
    sh[threadIdx.x] = v;
    __syncthreads();
#pragma unroll
    for (int off = 1; off < 256; off <<= 1) {
        int t = (threadIdx.x >= off) ? sh[threadIdx.x - off] : 0;
        __syncthreads();
        sh[threadIdx.x] += t;
        __syncthreads();
    }
    if (i < n) exc[i] = sh[threadIdx.x] - v;
    if (threadIdx.x == 255) bsums[blockIdx.x] = sh[255];
}

__global__ void scan_sums_k(int* __restrict__ bsums, int nb) {
    __shared__ int sh[512];
    int v = (threadIdx.x < nb) ? bsums[threadIdx.x] : 0;
    sh[threadIdx.x] = v;
    __syncthreads();
#pragma unroll
    for (int off = 1; off < 512; off <<= 1) {
        int t = (threadIdx.x >= off) ? sh[threadIdx.x - off] : 0;
        __syncthreads();
        sh[threadIdx.x] += t;
        __syncthreads();
    }
    if (threadIdx.x < nb) bsums[threadIdx.x] = sh[threadIdx.x] - v;  // exclusive
}

__global__ void scan_add_k(const int* __restrict__ exc, const int* __restrict__ bsums,
                           int* __restrict__ rowst, int* __restrict__ cursor,
                           int n, int e) {
    int i = blockIdx.x * 256 + threadIdx.x;
    if (i < n) {
        int r = exc[i] + bsums[i >> 8];
        rowst[i]  = r;
        cursor[i] = r;
    }
    if (i == 0) rowst[n] = e;
}

// ---------------- CSR fill ------------------------------------------------------
__global__ void fill_k(const int* __restrict__ src, const int* __restrict__ dst,
                       const float* __restrict__ dinv,
                       int* cursor, int* __restrict__ csrc, float* __restrict__ cnorm,
                       int e, int n) {
    int i = blockIdx.x * blockDim.x + threadIdx.x;
    if (i >= e) return;
    int s = src[i], d = dst[i];
    if ((unsigned)s >= (unsigned)n || (unsigned)d >= (unsigned)n) return;
    int pos = atomicAdd(&cursor[d], 1);
    csrc[pos]  = s;
    cnorm[pos] = dinv[s] * dinv[d];
}

// ---------------- fp32 GEMM, 8x8 register tile, fp16 output --------------------
// H[n,BN] (fp16) = A[n,128] @ W[128,BN]. 256 threads, split-tile addressing.
template<int BM, int BN>
__global__ void __launch_bounds__(256)
gemm_k(const float* __restrict__ A, const float* __restrict__ W,
       __half* __restrict__ H, int n)
{
    constexpr int K   = 128;
    constexpr int BK  = 16;
    constexpr int BMP = BM + 4;
    constexpr int COLG = BN / 8;
    static_assert((BM / 8) * COLG == 256, "256 threads");

    __shared__ float As[BK * BMP];           // transposed: As[k][row]
    __shared__ float Ws[BK * BN];            // Ws[k][col]

    const int tid = threadIdx.x;
    const int ty  = tid / COLG;
    const int tx  = tid % COLG;

    float acc[8][8];
#pragma unroll
    for (int i = 0; i < 8; i++)
#pragma unroll
        for (int j = 0; j < 8; j++) acc[i][j] = 0.0f;

    for (int k0 = 0; k0 < K; k0 += BK) {
#pragma unroll
        for (int p = 0; p < BM / 64; p++) {
            int idx  = p * 256 + tid;
            int row  = idx >> 2;
            int q    = (idx & 3) * 4;
            int grow = blockIdx.x * BM + row;
            float4 av = make_float4(0.f, 0.f, 0.f, 0.f);
            if (grow < n)
                av = *reinterpret_cast<const float4*>(A + (size_t)grow * K + k0 + q);
            As[(q + 0) * BMP + row] = av.x;
            As[(q + 1) * BMP + row] = av.y;
            As[(q + 2) * BMP + row] = av.z;
            As[(q + 3) * BMP + row] = av.w;
        }

#pragma unroll
        for (int p = 0; p < BN / 64; p++) {
            int idx = p * 256 + tid;
            int kk  = idx / (BN / 4);
            int cq  = (idx % (BN / 4)) * 4;
            *reinterpret_cast<float4*>(&Ws[kk * BN + cq]) =
                *reinterpret_cast<const float4*>(W + (size_t)(k0 + kk) * BN + cq);
        }
        __syncthreads();

#pragma unroll
        for (int kk = 0; kk < BK; kk++) {
            float4 a0 = *reinterpret_cast<const float4*>(&As[kk * BMP + ty * 4]);
            float4 a1 = *reinterpret_cast<const float4*>(&As[kk * BMP + BM / 2 + ty * 4]);
            float4 w0 = *reinterpret_cast<const float4*>(&Ws[kk * BN + tx * 4]);
            float4 w1 = *reinterpret_cast<const float4*>(&Ws[kk * BN + BN / 2 + tx * 4]);
            float ar[8] = {a0.x, a0.y, a0.z, a0.w, a1.x, a1.y, a1.z, a1.w};
            float wr[8] = {w0.x, w0.y, w0.z, w0.w, w1.x, w1.y, w1.z, w1.w};
#pragma unroll
            for (int i = 0; i < 8; i++)
#pragma unroll
                for (int j = 0; j < 8; j++)
                    acc[i][j] += ar[i] * wr[j];
        }
        __syncthreads();
    }

    // --- epilogue: convert to fp16, write two 4-half chunks per row ---
#pragma unroll
    for (int i = 0; i < 8; i++) {
        int rloc = (i < 4) ? (ty * 4 + i) : (BM / 2 + ty * 4 + i - 4);
        int row  = blockIdx.x * BM + rloc;
        if (row >= n) continue;
        __half2 p0 = __floats2half2_rn(acc[i][0], acc[i][1]);
        __half2 p1 = __floats2half2_rn(acc[i][2], acc[i][3]);
        __half2 p2 = __floats2half2_rn(acc[i][4], acc[i][5]);
        __half2 p3 = __floats2half2_rn(acc[i][6], acc[i][7]);
        *reinterpret_cast<__half2*>(H + (size_t)row * BN + tx * 4)              = p0;
        *reinterpret_cast<__half2*>(H + (size_t)row * BN + tx * 4 + 2)          = p1;
        *reinterpret_cast<__half2*>(H + (size_t)row * BN + BN / 2 + tx * 4)     = p2;
        *reinterpret_cast<__half2*>(H + (size_t)row * BN + BN / 2 + tx * 4 + 2) = p3;
    }
}

// ---------------- gather (fp16 h): out[d] = sum h[src]*norm + h[d]*dinv^2 + b --
// CH channels. Lane owns 4 channels (uint2 = 4 halves = 8B). CH/4 lanes per node.
template<int CH, bool RELU>
__global__ void __launch_bounds__(256)
gather_k(const int* __restrict__ rowst, const int* __restrict__ csrc,
         const float* __restrict__ cnorm, const __half* __restrict__ h,
         const float* __restrict__ dinv, const float* __restrict__ bias,
         float* __restrict__ out, int n)
{
    constexpr int LPN = CH / 4;                  // lanes per node (32 or 16)
    constexpr int NPW = 32 / LPN;                // nodes per warp (1 or 2)
    const int gtid = blockIdx.x * 256 + threadIdx.x;
    const int warp = gtid >> 5;
    const int lane = threadIdx.x & 31;
    const int sub  = lane / LPN;
    const int ln   = lane % LPN;                 // 4-channel chunk index
    const int node = warp * NPW + sub;
    if (node >= n) return;

    const uint2*  __restrict__ h8 = reinterpret_cast<const uint2*>(h);   // 4 halves
    const float4* __restrict__ b4 = reinterpret_cast<const float4*>(bias);

    const int start = rowst[node];
    const int end   = rowst[node + 1];

    float ax = 0.f, ay = 0.f, az = 0.f, aw = 0.f;

    int j = start;
    for (; j + 4 <= end; j += 4) {
        int   s0 = csrc[j],     s1 = csrc[j + 1], s2 = csrc[j + 2], s3 = csrc[j + 3];
        float n0 = cnorm[j],    n1 = cnorm[j + 1], n2 = cnorm[j + 2], n3 = cnorm[j + 3];
        uint2 u0 = h8[(size_t)s0 * LPN + ln];
        uint2 u1 = h8[(size_t)s1 * LPN + ln];
        uint2 u2 = h8[(size_t)s2 * LPN + ln];
        uint2 u3 = h8[(size_t)s3 * LPN + ln];
        float2 f0a = __half22float2(*reinterpret_cast<__half2*>(&u0.x));
        float2 f0b = __half22float2(*reinterpret_cast<__half2*>(&u0.y));
        float2 f1a = __half22float2(*reinterpret_cast<__half2*>(&u1.x));
        float2 f1b = __half22float2(*reinterpret_cast<__half2*>(&u1.y));
        float2 f2a = __half22float2(*reinterpret_cast<__half2*>(&u2.x));
        float2 f2b = __half22float2(*reinterpret_cast<__half2*>(&u2.y));
        float2 f3a = __half22float2(*reinterpret_cast<__half2*>(&u3.x));
        float2 f3b = __half22float2(*reinterpret_cast<__half2*>(&u3.y));
        ax += f0a.x * n0 + f1a.x * n1 + f2a.x * n2 + f3a.x * n3;
        ay += f0a.y * n0 + f1a.y * n1 + f2a.y * n2 + f3a.y * n3;
        az += f0b.x * n0 + f1b.x * n1 + f2b.x * n2 + f3b.x * n3;
        aw += f0b.y * n0 + f1b.y * n1 + f2b.y * n2 + f3b.y * n3;
    }
    for (; j < end; ++j) {
        int s = csrc[j];
        float nn = cnorm[j];
        uint2 u = h8[(size_t)s * LPN + ln];
        float2 fa = __half22float2(*reinterpret_cast<__half2*>(&u.x));
        float2 fb = __half22float2(*reinterpret_cast<__half2*>(&u.y));
        ax += fa.x * nn; ay += fa.y * nn; az += fb.x * nn; aw += fb.y * nn;
    }

    // self-loop + bias
    float di  = dinv[node];
    float di2 = di * di;
    uint2 us = h8[(size_t)node * LPN + ln];
    float2 sa = __half22float2(*reinterpret_cast<__half2*>(&us.x));
    float2 sb = __half22float2(*reinterpret_cast<__half2*>(&us.y));
    float4 bb = b4[ln];
    ax += sa.x * di2 + bb.x;
    ay += sa.y * di2 + bb.y;
    az += sb.x * di2 + bb.z;
    aw += sb.y * di2 + bb.w;
    if (RELU) {
        ax = fmaxf(ax, 0.f); ay = fmaxf(ay, 0.f);
        az = fmaxf(az, 0.f); aw = fmaxf(aw, 0.f);
    }
    reinterpret_cast<float4*>(out)[(size_t)node * LPN + ln] = make_float4(ax, ay, az, aw);
}

// ---------------- launcher ----------------------------------------------------
extern "C" void kernel_launch(void* const* d_in, const int* in_sizes, int n_in,
                              void* d_out, int out_size)
{
    const float* x   = (const float*)d_in[0];
    const int*   ei  = (const int*)d_in[1];
    const float* W1  = (const float*)d_in[2];
    const float* b1  = (const float*)d_in[3];
    const float* W2  = (const float*)d_in[4];
    const float* b2  = (const float*)d_in[5];
    float*       out = (float*)d_out;

    const int n = in_sizes[0] / INCH;
    const int e = in_sizes[1] / 2;
    const int* src = ei;
    const int* dst = ei + e;

    int *counts, *exc, *bsums, *rowst, *cursor, *csrc;
    float *cnorm, *dinv, *hbuf;
    __half *h1, *h2;
    cudaGetSymbolAddress((void**)&counts, g_counts);
    cudaGetSymbolAddress((void**)&exc,    g_exc);
    cudaGetSymbolAddress((void**)&bsums,  g_bsums);
    cudaGetSymbolAddress((void**)&rowst,  g_rowst);
    cudaGetSymbolAddress((void**)&cursor, g_cursor);
    cudaGetSymbolAddress((void**)&csrc,   g_csrc);
    cudaGetSymbolAddress((void**)&cnorm,  g_cnorm);
    cudaGetSymbolAddress((void**)&dinv,   g_dinv);
    cudaGetSymbolAddress((void**)&h1,     g_h1);
    cudaGetSymbolAddress((void**)&hbuf,   g_hbuf);
    cudaGetSymbolAddress((void**)&h2,     g_h2);

    const int T = 256;
    const int nb = (n + 255) / 256;

    // ---- degree + CSR build ----
    zero_counts_k<<<(n + T - 1) / T, T>>>(counts, n);
    count_k      <<<(e + T - 1) / T, T>>>(dst, counts, e, n);
    dinv_k       <<<(n + T - 1) / T, T>>>(counts, dinv, n);
    scan_block_k <<<nb, 256>>>(counts, exc, bsums, n);
    scan_sums_k  <<<1, 512>>>(bsums, nb);
    scan_add_k   <<<nb, 256>>>(exc, bsums, rowst, cursor, n, e);
    fill_k       <<<(e + T - 1) / T, T>>>(src, dst, dinv, cursor, csrc, cnorm, e, n);

    // ---- layer 1: h1 = fp16(x@W1) ; hbuf = relu(gather(h1) + self + b1) ----
    gemm_k<128, HIDCH><<<(n + 127) / 128, 256>>>(x, W1, h1, n);
    {
        int warps = n;                            // 1 node per warp (128ch)
        gather_k<HIDCH, true><<<(warps * 32 + 255) / 256, 256>>>(
            rowst, csrc, cnorm, h1, dinv, b1, hbuf, n);
    }

    // ---- layer 2: h2 = fp16(hbuf@W2) ; out = gather(h2) + self + b2 ----
    gemm_k<256, OUTCH><<<(n + 255) / 256, 256>>>(hbuf, W2, h2, n);
    {
        int warps = (n + 1) / 2;                  // 2 nodes per warp (64ch)
        gather_k<OUTCH, false><<<(warps * 32 + 255) / 256, 256>>>(
            rowst, csrc, cnorm, h2, dinv, b2, out, n);
    }
}